// round 14
// baseline (speedup 1.0000x reference)
#include <cuda_runtime.h>
#include <cstdint>
#include <math.h>

// Phase 1: energies[b*2048 + s] = dot(hidden[b,:], enc[s,b,:])
// Block = (s-group of 8) x (b-group of 8). Warp w owns row s0+w and loops
// over b0..b0+7: rows (s, b0..b0+7) are CONTIGUOUS in memory, so each warp
// streams one sequential 32KB run (vs scattered 4KB granules in R7).
// Inner loop keeps the proven R7 register profile: ONE live accumulator,
// 8 independent __ldcs float4 in flight, hv re-read from smem per row.
__global__ void __launch_bounds__(256) dot_kernel(
    const float* __restrict__ hidden,   // [64, 1024]
    const float* __restrict__ enc,      // [2048, 64, 1024]
    float* __restrict__ energies)       // [64, 2048]
{
    cudaTriggerProgrammaticLaunchCompletion();

    __shared__ float4 sh_h[8 * 256];    // hidden[b0..b0+7], 32KB

    // grid = 256 s-groups x 8 b-groups = 2048 blocks
    int sg = blockIdx.x >> 3;           // 0..255
    int bg = blockIdx.x & 7;            // 0..7
    int b0 = bg * 8;

    // stage 8 hidden rows (32KB) cooperatively: 2048 float4 / 256 thr = 8 each
#pragma unroll
    for (int i = 0; i < 8; i++)
        sh_h[threadIdx.x + i * 256] =
            reinterpret_cast<const float4*>(hidden)[b0 * 256 + threadIdx.x + i * 256];
    __syncthreads();

    int warp = threadIdx.x >> 5;
    int lane = threadIdx.x & 31;
    int s    = sg * 8 + warp;

    // warp's contiguous 32KB: rows (s, b0) .. (s, b0+7)
    const float4* base = reinterpret_cast<const float4*>(
        enc + ((size_t)s * 64 + b0) * 1024);

#pragma unroll
    for (int j = 0; j < 8; j++) {
        const float4* row = base + j * 256;
        const float4* hv4 = &sh_h[j * 256];
        float acc = 0.0f;
#pragma unroll
        for (int i = 0; i < 8; i++) {
            float4 e  = __ldcs(&row[lane + i * 32]);
            float4 hv = hv4[lane + i * 32];
            acc = fmaf(e.x, hv.x, acc);
            acc = fmaf(e.y, hv.y, acc);
            acc = fmaf(e.z, hv.z, acc);
            acc = fmaf(e.w, hv.w, acc);
        }
#pragma unroll
        for (int o = 16; o; o >>= 1)
            acc += __shfl_xor_sync(0xffffffffu, acc, o);
        if (lane == 0)
            energies[(b0 + j) * 2048 + s] = acc;
    }
}

// Phase 2: warp-per-row softmax (identical to the 80.4us run), PDL-overlapped.
__global__ void __launch_bounds__(32) softmax_kernel(float* __restrict__ out)
{
    int b    = blockIdx.x;
    int lane = threadIdx.x;
    float* p = out + (size_t)b * 2048;

    cudaGridDependencySynchronize();

    const float4* pv = reinterpret_cast<const float4*>(p);
    float4 v[16];
#pragma unroll
    for (int i = 0; i < 16; i++)
        v[i] = __ldcg(&pv[lane + i * 32]);

    float m = -INFINITY;
#pragma unroll
    for (int i = 0; i < 16; i++)
        m = fmaxf(m, fmaxf(fmaxf(v[i].x, v[i].y), fmaxf(v[i].z, v[i].w)));
#pragma unroll
    for (int o = 16; o; o >>= 1)
        m = fmaxf(m, __shfl_xor_sync(0xffffffffu, m, o));

    float s = 0.0f;
#pragma unroll
    for (int i = 0; i < 16; i++) {
        v[i].x = __expf(v[i].x - m);
        v[i].y = __expf(v[i].y - m);
        v[i].z = __expf(v[i].z - m);
        v[i].w = __expf(v[i].w - m);
        s += (v[i].x + v[i].y) + (v[i].z + v[i].w);
    }
#pragma unroll
    for (int o = 16; o; o >>= 1)
        s += __shfl_xor_sync(0xffffffffu, s, o);
    float inv = 1.0f / s;

    float4* pw = reinterpret_cast<float4*>(p);
#pragma unroll
    for (int i = 0; i < 16; i++) {
        float4 w = v[i];
        w.x *= inv; w.y *= inv; w.z *= inv; w.w *= inv;
        pw[lane + i * 32] = w;
    }
}

extern "C" void kernel_launch(void* const* d_in, const int* in_sizes, int n_in,
                              void* d_out, int out_size)
{
    const float* hidden = (const float*)d_in[0];   // [1, 64, 1024]
    const float* enc    = (const float*)d_in[1];   // [2048, 64, 1024]
    float* out          = (float*)d_out;           // [64, 1, 2048]

    dot_kernel<<<2048, 256>>>(hidden, enc, out);

    cudaLaunchConfig_t cfg = {};
    cfg.gridDim  = dim3(64, 1, 1);
    cfg.blockDim = dim3(32, 1, 1);
    cfg.dynamicSmemBytes = 0;
    cfg.stream = 0;
    cudaLaunchAttribute attrs[1];
    attrs[0].id = cudaLaunchAttributeProgrammaticStreamSerialization;
    attrs[0].val.programmaticStreamSerializationAllowed = 1;
    cfg.attrs = attrs;
    cfg.numAttrs = 1;
    cudaLaunchKernelEx(&cfg, softmax_kernel, out);
}

// round 15
// speedup vs baseline: 1.0930x; 1.0930x over previous
#include <cuda_runtime.h>
#include <cstdint>
#include <math.h>

// Single kernel. Cluster = 8 CTAs x 256 thr = one batch b (grid 512 -> all SMs,
// ~3.5 CTAs/SM, R7-like warp pool). Each CTA: 256 rows of energies[b] into
// smem with the exact R7 dot loop; batch-wide max/sum via DSMEM mailboxes +
// barrier.cluster (proven in R11). No gmem energies round-trip, no 5us
// kernel-boundary tail, no gpu-scope atomics.

__global__ void __launch_bounds__(256) __cluster_dims__(8, 1, 1)
attn_cluster_kernel(const float* __restrict__ hidden,   // [64, 1024]
                    const float* __restrict__ enc,      // [2048, 64, 1024]
                    float* __restrict__ out)            // [64, 2048]
{
    __shared__ float4 sh_h[256];   // hidden[b], 4KB
    __shared__ float  sh_e[256];   // this CTA's 256 energies
    __shared__ float  red[8];      // per-warp partials
    __shared__ float  mailM[8];    // cluster max partials (one slot per rank)
    __shared__ float  mailS[8];    // cluster sum partials

    int tid  = threadIdx.x;
    int warp = tid >> 5;
    int lane = tid & 31;

    unsigned int rank;
    asm("mov.u32 %0, %%cluster_ctarank;" : "=r"(rank));
    int b = blockIdx.x >> 3;

    sh_h[tid] = reinterpret_cast<const float4*>(hidden + (size_t)b * 1024)[tid];
    __syncthreads();

    // ---- dot: warp w computes rows rank*256 + w*32 .. +31 (R7 inner body) ----
    int s0 = (int)rank * 256 + warp * 32;
    for (int r = 0; r < 32; r++) {
        const float4* row = reinterpret_cast<const float4*>(
            enc + ((size_t)(s0 + r) * 64 + b) * 1024);
        float acc = 0.0f;
#pragma unroll
        for (int i = 0; i < 8; i++) {
            float4 e  = __ldcs(&row[lane + i * 32]);
            float4 hv = sh_h[lane + i * 32];
            acc = fmaf(e.x, hv.x, acc);
            acc = fmaf(e.y, hv.y, acc);
            acc = fmaf(e.z, hv.z, acc);
            acc = fmaf(e.w, hv.w, acc);
        }
#pragma unroll
        for (int o = 16; o; o >>= 1)
            acc += __shfl_xor_sync(0xffffffffu, acc, o);
        if (lane == 0)
            sh_e[warp * 32 + r] = acc;
    }
    __syncthreads();

    // ---- local max over 256 values (1/thread) ----
    float m = sh_e[tid];
#pragma unroll
    for (int o = 16; o; o >>= 1)
        m = fmaxf(m, __shfl_xor_sync(0xffffffffu, m, o));
    if (lane == 0) red[warp] = m;
    __syncthreads();
    if (tid == 0) {
        float x = red[0];
#pragma unroll
        for (int i = 1; i < 8; i++) x = fmaxf(x, red[i]);
        // broadcast my partial max into every cluster CTA's mailM[rank]
        unsigned int la = (unsigned int)__cvta_generic_to_shared(&mailM[rank]);
#pragma unroll
        for (unsigned int t = 0; t < 8; t++) {
            unsigned int pa;
            asm("mapa.shared::cluster.u32 %0, %1, %2;"
                : "=r"(pa) : "r"(la), "r"(t));
            asm volatile("st.shared::cluster.f32 [%0], %1;"
                         :: "r"(pa), "f"(x) : "memory");
        }
    }
    asm volatile("barrier.cluster.arrive.aligned;" ::: "memory");
    asm volatile("barrier.cluster.wait.aligned;"   ::: "memory");
    float gm = mailM[0];
#pragma unroll
    for (int i = 1; i < 8; i++) gm = fmaxf(gm, mailM[i]);

    // ---- exp + local sum ----
    float e = __expf(sh_e[tid] - gm);
    sh_e[tid] = e;
    float s = e;
#pragma unroll
    for (int o = 16; o; o >>= 1)
        s += __shfl_xor_sync(0xffffffffu, s, o);
    if (lane == 0) red[warp] = s;
    __syncthreads();
    if (tid == 0) {
        float x = red[0];
#pragma unroll
        for (int i = 1; i < 8; i++) x += red[i];
        unsigned int la = (unsigned int)__cvta_generic_to_shared(&mailS[rank]);
#pragma unroll
        for (unsigned int t = 0; t < 8; t++) {
            unsigned int pa;
            asm("mapa.shared::cluster.u32 %0, %1, %2;"
                : "=r"(pa) : "r"(la), "r"(t));
            asm volatile("st.shared::cluster.f32 [%0], %1;"
                         :: "r"(pa), "f"(x) : "memory");
        }
    }
    asm volatile("barrier.cluster.arrive.aligned;" ::: "memory");
    asm volatile("barrier.cluster.wait.aligned;"   ::: "memory");
    float gs = mailS[0];
#pragma unroll
    for (int i = 1; i < 8; i++) gs += mailS[i];
    float inv = 1.0f / gs;

    // ---- write this CTA's 256 probabilities (coalesced 1KB) ----
    out[(size_t)b * 2048 + rank * 256 + tid] = sh_e[tid] * inv;
}

extern "C" void kernel_launch(void* const* d_in, const int* in_sizes, int n_in,
                              void* d_out, int out_size)
{
    const float* hidden = (const float*)d_in[0];   // [1, 64, 1024]
    const float* enc    = (const float*)d_in[1];   // [2048, 64, 1024]
    float* out          = (float*)d_out;           // [64, 1, 2048]

    // 64 batches x cluster(8) = 512 CTAs of 256 threads
    attn_cluster_kernel<<<512, 256>>>(hidden, enc, out);
}